// round 1
// baseline (speedup 1.0000x reference)
#include <cuda_runtime.h>
#include <cstdint>

#define NMAX 4096
#define HID 64

// ---------------- device scratch (no allocations allowed) ----------------
__device__ __align__(256) float g_P[NMAX * HID];        // per-node layer1 precompute
__device__ __align__(256) float g_agg[NMAX * HID];      // segment_sum result h
__device__ __align__(256) float g_q[4 * NMAX * 16];
__device__ __align__(256) float g_k[4 * NMAX * 16];
__device__ __align__(256) float g_v[4 * NMAX * 16];
__device__ __align__(256) float g_obuf[NMAX * HID];     // attention output (pre out_proj)
__device__ int g_is64_ei;
__device__ int g_is64_ty;

__device__ __forceinline__ long ldidx(const void* p, long i, int is64) {
    return is64 ? (long)((const long long*)p)[i] : (long)((const int*)p)[i];
}

// ---------------- dtype detection: int64 (high words all zero) vs int32 ----
__global__ void detect_kernel(const unsigned* ei, const unsigned* ty) {
    if (threadIdx.x == 0) {
        unsigned a = 0;
        for (int i = 0; i < 32; i++) a |= ei[2 * i + 1];
        g_is64_ei = (a == 0) ? 1 : 0;
        unsigned b = 0;
        for (int i = 0; i < 32; i++) b |= ty[2 * i + 1];
        g_is64_ty = (b == 0) ? 1 : 0;
    }
}

__global__ void zero_kernel(int n) {
    int i = blockIdx.x * blockDim.x + threadIdx.x;
    if (i < n) g_agg[i] = 0.f;
}

// ---------------- P[n][d] = b1[d] + sum_{k<14} xe[n][k] * w1[d][k] -----------
__global__ void prep_kernel(const float* __restrict__ x, const float* __restrict__ emb,
                            const float* __restrict__ w1, const float* __restrict__ b1,
                            const void* __restrict__ ety) {
    int n = blockIdx.x, d = threadIdx.x;
    __shared__ float xs[14];
    int is64 = g_is64_ty;
    if (d < 6) {
        xs[d] = x[n * 6 + d];
    } else if (d < 14) {
        long t = ldidx(ety, n, is64);
        xs[d] = emb[t * 8 + (d - 6)];
    }
    __syncthreads();
    float acc = b1[d];
#pragma unroll
    for (int k = 0; k < 14; k++) acc = fmaf(xs[k], w1[d * 15 + k], acc);
    g_P[n * HID + d] = acc;
}

// ---------------- edge MLP + scatter-add ------------------------------------
// Block = 64 threads (one "crew"), thread d owns output dim d, 4 edges/iter,
// 128 edges/block. Layer-2 weights register-resident; LN via shuffle + smem.
__global__ void __launch_bounds__(64) edge_kernel(
    const void* __restrict__ ei, const float* __restrict__ eattr,
    const float* __restrict__ w1, const float* __restrict__ w2g,
    const float* __restrict__ b2g, const float* __restrict__ lng,
    const float* __restrict__ lnb, int nE) {
    int d = threadIdx.x;
    int lane = d & 31, wrp = d >> 5;
    int is64 = g_is64_ei;

    float w1l = w1[d * 15 + 14];
    float b2 = b2g[d], gg = lng[d], gb = lnb[d];
    float w2[64];
    {
        const float4* p4 = (const float4*)(w2g + d * 64);
#pragma unroll
        for (int k = 0; k < 16; k++) {
            float4 f = p4[k];
            w2[4 * k] = f.x; w2[4 * k + 1] = f.y; w2[4 * k + 2] = f.z; w2[4 * k + 3] = f.w;
        }
    }

    __shared__ __align__(16) float h1s[4][64];
    __shared__ __align__(16) float h2s[4][64];
    __shared__ float part[2][8];
    __shared__ int ssrc[4];
    __shared__ int sdst[4];
    __shared__ float sat[4];

    long base = (long)blockIdx.x * 128;
    for (int it = 0; it < 32; it++) {
        if (d < 4) {
            long eg = base + it * 4 + d;
            if (eg < nE) {
                ssrc[d] = (int)ldidx(ei, eg, is64);
                sdst[d] = (int)ldidx(ei, (long)nE + eg, is64);
                sat[d] = eattr[eg];
            } else {
                ssrc[d] = 0; sdst[d] = -1; sat[d] = 0.f;
            }
        }
        __syncthreads();

        // layer 1: pre = P[src] + a_e * w1_last, relu
        float v[4];
#pragma unroll
        for (int e = 0; e < 4; e++) {
            float pre = fmaf(sat[e], w1l, g_P[ssrc[e] * HID + d]);
            v[e] = fmaxf(pre, 0.f);
        }
        // LayerNorm 1 (over 64 dims = 64 threads, 2 warps)
        {
            float s[4], q[4];
#pragma unroll
            for (int e = 0; e < 4; e++) { s[e] = v[e]; q[e] = v[e] * v[e]; }
#pragma unroll
            for (int off = 16; off > 0; off >>= 1) {
#pragma unroll
                for (int e = 0; e < 4; e++) {
                    s[e] += __shfl_xor_sync(0xffffffffu, s[e], off);
                    q[e] += __shfl_xor_sync(0xffffffffu, q[e], off);
                }
            }
            if (lane == 0) {
#pragma unroll
                for (int e = 0; e < 4; e++) { part[wrp][e] = s[e]; part[wrp][4 + e] = q[e]; }
            }
            __syncthreads();
#pragma unroll
            for (int e = 0; e < 4; e++) {
                float S = part[0][e] + part[1][e];
                float Q = part[0][4 + e] + part[1][4 + e];
                float mean = S * (1.f / 64.f);
                float var = Q * (1.f / 64.f) - mean * mean;
                float r = rsqrtf(var + 1e-5f);
                v[e] = (v[e] - mean) * r * gg + gb;
                h1s[e][d] = v[e];
            }
        }
        __syncthreads();

        // layer 2: 64x64 GEMV per edge, weights in regs, inputs broadcast from smem
        float a2[4];
#pragma unroll
        for (int e = 0; e < 4; e++) a2[e] = b2;
#pragma unroll
        for (int k = 0; k < 16; k++) {
#pragma unroll
            for (int e = 0; e < 4; e++) {
                float4 h = *(const float4*)&h1s[e][k * 4];
                a2[e] = fmaf(w2[4 * k], h.x, a2[e]);
                a2[e] = fmaf(w2[4 * k + 1], h.y, a2[e]);
                a2[e] = fmaf(w2[4 * k + 2], h.z, a2[e]);
                a2[e] = fmaf(w2[4 * k + 3], h.w, a2[e]);
            }
        }
#pragma unroll
        for (int e = 0; e < 4; e++) v[e] = fmaxf(a2[e], 0.f);
        // LayerNorm 2 (same g/b per reference)
        {
            float s[4], q[4];
#pragma unroll
            for (int e = 0; e < 4; e++) { s[e] = v[e]; q[e] = v[e] * v[e]; }
#pragma unroll
            for (int off = 16; off > 0; off >>= 1) {
#pragma unroll
                for (int e = 0; e < 4; e++) {
                    s[e] += __shfl_xor_sync(0xffffffffu, s[e], off);
                    q[e] += __shfl_xor_sync(0xffffffffu, q[e], off);
                }
            }
            if (lane == 0) {
#pragma unroll
                for (int e = 0; e < 4; e++) { part[wrp][e] = s[e]; part[wrp][4 + e] = q[e]; }
            }
            __syncthreads();
#pragma unroll
            for (int e = 0; e < 4; e++) {
                float S = part[0][e] + part[1][e];
                float Q = part[0][4 + e] + part[1][4 + e];
                float mean = S * (1.f / 64.f);
                float var = Q * (1.f / 64.f) - mean * mean;
                float r = rsqrtf(var + 1e-5f);
                h2s[e][d] = (v[e] - mean) * r * gg + gb;
            }
        }
        __syncthreads();

        // scatter-add: vectorized red, thread t handles (edge t>>4, 4 dims)
        {
            int e = d >> 4, c = d & 15;
            int dn = sdst[e];
            if (dn >= 0) {
                float4 val = *(const float4*)&h2s[e][c * 4];
                float* p = &g_agg[dn * HID + c * 4];
                asm volatile("red.global.add.v4.f32 [%0], {%1,%2,%3,%4};"
                             :: "l"(p), "f"(val.x), "f"(val.y), "f"(val.z), "f"(val.w)
                             : "memory");
            }
        }
        __syncthreads();
    }
}

// ---------------- qkv = h @ in_proj_w.T + b, split into head-major q/k/v ----
__global__ void __launch_bounds__(192) qkv_kernel(const float* __restrict__ w,
                                                  const float* __restrict__ b, int N) {
    __shared__ __align__(16) float hs[16 * 64];
    int tid = threadIdx.x;
    int n0 = blockIdx.x * 16;
    for (int i = tid; i < 16 * 64; i += 192) hs[i] = g_agg[n0 * 64 + i];
    float wr[64];
    {
        const float4* p4 = (const float4*)(w + tid * 64);
#pragma unroll
        for (int k = 0; k < 16; k++) {
            float4 f = p4[k];
            wr[4 * k] = f.x; wr[4 * k + 1] = f.y; wr[4 * k + 2] = f.z; wr[4 * k + 3] = f.w;
        }
    }
    float br = b[tid];
    __syncthreads();
    int sec = tid / 64, wi = tid % 64, hh = wi / 16, dd = wi % 16;
    float* dst = sec == 0 ? g_q : (sec == 1 ? g_k : g_v);
#pragma unroll 4
    for (int nn = 0; nn < 16; nn++) {
        float acc = br;
#pragma unroll
        for (int k = 0; k < 16; k++) {
            float4 h = *(const float4*)&hs[nn * 64 + 4 * k];
            acc = fmaf(wr[4 * k], h.x, acc);
            acc = fmaf(wr[4 * k + 1], h.y, acc);
            acc = fmaf(wr[4 * k + 2], h.z, acc);
            acc = fmaf(wr[4 * k + 3], h.w, acc);
        }
        dst[hh * N * 16 + (n0 + nn) * 16 + dd] = acc;
    }
}

// ---------------- flash attention, fp32, online softmax ---------------------
// Block = 128 threads: 64 queries x 2 key-halves. grid = (N/64, 4 heads).
__global__ void __launch_bounds__(128) attn_kernel(int N) {
    int hh = blockIdx.y;
    int half = threadIdx.x >> 6;
    int qi = threadIdx.x & 63;
    int n = blockIdx.x * 64 + qi;
    const float* Q = g_q + hh * N * 16;
    const float* K = g_k + hh * N * 16;
    const float* V = g_v + hh * N * 16;

    float q[16];
    {
        const float4* qp = (const float4*)(Q + n * 16);
#pragma unroll
        for (int u = 0; u < 4; u++) {
            float4 f = qp[u];
            q[4 * u] = f.x; q[4 * u + 1] = f.y; q[4 * u + 2] = f.z; q[4 * u + 3] = f.w;
        }
    }
    float o[16];
#pragma unroll
    for (int c = 0; c < 16; c++) o[c] = 0.f;
    float m = -1e30f, l = 0.f;

    __shared__ __align__(16) float Ks[128 * 16];
    __shared__ __align__(16) float Vs[128 * 16];
    __shared__ __align__(16) float mrg[64 * 18];

    for (int kt = 0; kt < N; kt += 128) {
        {
            int r = threadIdx.x;
            const float4* kp = (const float4*)(K + (kt + r) * 16);
            const float4* vp = (const float4*)(V + (kt + r) * 16);
            float4* kd = (float4*)&Ks[r * 16];
            float4* vd = (float4*)&Vs[r * 16];
#pragma unroll
            for (int u = 0; u < 4; u++) { kd[u] = kp[u]; vd[u] = vp[u]; }
        }
        __syncthreads();
        int j0 = half * 64;
        for (int j = j0; j < j0 + 64; j++) {
            const float4* kr = (const float4*)&Ks[j * 16];
            float4 k0 = kr[0], k1 = kr[1], k2 = kr[2], k3 = kr[3];
            float s0 = q[0] * k0.x + q[1] * k0.y + q[2] * k0.z + q[3] * k0.w;
            float s1 = q[4] * k1.x + q[5] * k1.y + q[6] * k1.z + q[7] * k1.w;
            float s2 = q[8] * k2.x + q[9] * k2.y + q[10] * k2.z + q[11] * k2.w;
            float s3 = q[12] * k3.x + q[13] * k3.y + q[14] * k3.z + q[15] * k3.w;
            float s = ((s0 + s1) + (s2 + s3)) * 0.25f;
            float nm = fmaxf(m, s);
            float p = __expf(s - nm);
            if (nm > m) {
                float corr = __expf(m - nm);
                l *= corr;
#pragma unroll
                for (int c = 0; c < 16; c++) o[c] *= corr;
                m = nm;
            }
            l += p;
            const float4* vr = (const float4*)&Vs[j * 16];
            float4 v0 = vr[0], v1 = vr[1], v2 = vr[2], v3 = vr[3];
            o[0] = fmaf(p, v0.x, o[0]);  o[1] = fmaf(p, v0.y, o[1]);
            o[2] = fmaf(p, v0.z, o[2]);  o[3] = fmaf(p, v0.w, o[3]);
            o[4] = fmaf(p, v1.x, o[4]);  o[5] = fmaf(p, v1.y, o[5]);
            o[6] = fmaf(p, v1.z, o[6]);  o[7] = fmaf(p, v1.w, o[7]);
            o[8] = fmaf(p, v2.x, o[8]);  o[9] = fmaf(p, v2.y, o[9]);
            o[10] = fmaf(p, v2.z, o[10]); o[11] = fmaf(p, v2.w, o[11]);
            o[12] = fmaf(p, v3.x, o[12]); o[13] = fmaf(p, v3.y, o[13]);
            o[14] = fmaf(p, v3.z, o[14]); o[15] = fmaf(p, v3.w, o[15]);
        }
        __syncthreads();
    }
    // merge the two key-halves per query
    if (half == 1) {
        float* dstp = &mrg[qi * 18];
        dstp[0] = m; dstp[1] = l;
#pragma unroll
        for (int c = 0; c < 16; c++) dstp[2 + c] = o[c];
    }
    __syncthreads();
    if (half == 0) {
        const float* sp = &mrg[qi * 18];
        float m1 = sp[0], l1 = sp[1];
        float M = fmaxf(m, m1);
        float c0 = __expf(m - M), c1 = __expf(m1 - M);
        float L = l * c0 + l1 * c1;
        float inv = 1.f / L;
#pragma unroll
        for (int c = 0; c < 16; c++) {
            float oc = o[c] * c0 + sp[2 + c] * c1;
            g_obuf[n * 64 + hh * 16 + c] = oc * inv;
        }
    }
}

// ---------------- out_proj + residual + LN + final linear --------------------
__global__ void __launch_bounds__(64) epi_kernel(
    const float* __restrict__ opw, const float* __restrict__ opb,
    const float* __restrict__ ang, const float* __restrict__ anb,
    const float* __restrict__ ow, const float* __restrict__ ob,
    float* __restrict__ out) {
    int d = threadIdx.x;
    int n0 = blockIdx.x * 8;
    __shared__ __align__(16) float os[8 * 64];
    __shared__ __align__(16) float ts[8 * 64];
    __shared__ float ps[8][8], pq[8][8];
    __shared__ float mv[8][2];

    for (int i = d; i < 8 * 64; i += 64) os[i] = g_obuf[n0 * 64 + i];
    float wr[64];
    {
        const float4* p4 = (const float4*)(opw + d * 64);
#pragma unroll
        for (int k = 0; k < 16; k++) {
            float4 f = p4[k];
            wr[4 * k] = f.x; wr[4 * k + 1] = f.y; wr[4 * k + 2] = f.z; wr[4 * k + 3] = f.w;
        }
    }
    float bb = opb[d];
    __syncthreads();
#pragma unroll
    for (int nn = 0; nn < 8; nn++) {
        float acc = bb;
#pragma unroll
        for (int k = 0; k < 16; k++) {
            float4 h = *(const float4*)&os[nn * 64 + 4 * k];
            acc = fmaf(wr[4 * k], h.x, acc);
            acc = fmaf(wr[4 * k + 1], h.y, acc);
            acc = fmaf(wr[4 * k + 2], h.z, acc);
            acc = fmaf(wr[4 * k + 3], h.w, acc);
        }
        ts[nn * 64 + d] = g_agg[(n0 + nn) * 64 + d] + acc;
    }
    __syncthreads();
    {
        int n = d >> 3, sg = d & 7;
        float s = 0.f, qq = 0.f;
#pragma unroll
        for (int t = 0; t < 8; t++) {
            float v2 = ts[n * 64 + sg * 8 + t];
            s += v2; qq += v2 * v2;
        }
        ps[n][sg] = s; pq[n][sg] = qq;
    }
    __syncthreads();
    if (d < 8) {
        float s = 0.f, qq = 0.f;
#pragma unroll
        for (int t = 0; t < 8; t++) { s += ps[d][t]; qq += pq[d][t]; }
        float mean = s * (1.f / 64.f);
        float var = qq * (1.f / 64.f) - mean * mean;
        mv[d][0] = mean;
        mv[d][1] = rsqrtf(var + 1e-5f);
    }
    __syncthreads();
    float gg = ang[d], gb = anb[d];
#pragma unroll
    for (int nn = 0; nn < 8; nn++)
        ts[nn * 64 + d] = (ts[nn * 64 + d] - mv[nn][0]) * mv[nn][1] * gg + gb;
    {
        const float4* p4 = (const float4*)(ow + d * 64);
#pragma unroll
        for (int k = 0; k < 16; k++) {
            float4 f = p4[k];
            wr[4 * k] = f.x; wr[4 * k + 1] = f.y; wr[4 * k + 2] = f.z; wr[4 * k + 3] = f.w;
        }
    }
    float bo = ob[d];
    __syncthreads();
#pragma unroll
    for (int nn = 0; nn < 8; nn++) {
        float acc = bo;
#pragma unroll
        for (int k = 0; k < 16; k++) {
            float4 h = *(const float4*)&ts[nn * 64 + 4 * k];
            acc = fmaf(wr[4 * k], h.x, acc);
            acc = fmaf(wr[4 * k + 1], h.y, acc);
            acc = fmaf(wr[4 * k + 2], h.z, acc);
            acc = fmaf(wr[4 * k + 3], h.w, acc);
        }
        out[(n0 + nn) * 64 + d] = acc;
    }
}

// ---------------- launch ----------------
extern "C" void kernel_launch(void* const* d_in, const int* in_sizes, int n_in,
                              void* d_out, int out_size) {
    const float* x        = (const float*)d_in[0];
    const float* eattr    = (const float*)d_in[1];
    const float* emb      = (const float*)d_in[2];
    const float* lin1_w   = (const float*)d_in[3];
    const float* lin1_b   = (const float*)d_in[4];
    const float* lay_w    = (const float*)d_in[5];
    const float* lay_b    = (const float*)d_in[6];
    const float* ln_g     = (const float*)d_in[7];
    const float* ln_b     = (const float*)d_in[8];
    const float* in_proj_w  = (const float*)d_in[9];
    const float* in_proj_b  = (const float*)d_in[10];
    const float* out_proj_w = (const float*)d_in[11];
    const float* out_proj_b = (const float*)d_in[12];
    const float* an_g     = (const float*)d_in[13];
    const float* an_b     = (const float*)d_in[14];
    const float* out_w    = (const float*)d_in[15];
    const float* out_b    = (const float*)d_in[16];
    const void*  ei       = d_in[17];
    const void*  ety      = d_in[18];

    int E = in_sizes[1];          // edge_attr is [E,1]
    int N = in_sizes[0] / 6;      // x is [N,6]

    detect_kernel<<<1, 32>>>((const unsigned*)ei, (const unsigned*)ety);
    zero_kernel<<<(N * HID + 255) / 256, 256>>>(N * HID);
    prep_kernel<<<N, 64>>>(x, emb, lin1_w, lin1_b, ety);
    edge_kernel<<<(E + 127) / 128, 64>>>(ei, eattr, lin1_w, lay_w, lay_b, ln_g, ln_b, E);
    qkv_kernel<<<N / 16, 192>>>(in_proj_w, in_proj_b, N);
    attn_kernel<<<dim3(N / 64, 4), 128>>>(N);
    epi_kernel<<<N / 8, 64>>>(out_proj_w, out_proj_b, an_g, an_b, out_w, out_b,
                              (float*)d_out);
}

// round 2
// speedup vs baseline: 1.3312x; 1.3312x over previous
#include <cuda_runtime.h>
#include <cstdint>

#define NMAX 4096
#define HID 64

typedef unsigned long long ull;

// ---------------- device scratch ----------------
__device__ __align__(256) float g_P[NMAX * HID];
__device__ __align__(256) float g_agg[NMAX * HID];
__device__ __align__(256) float g_q[4 * NMAX * 16];
__device__ __align__(256) float g_k[4 * NMAX * 16];
__device__ __align__(256) float g_v[4 * NMAX * 16];
__device__ __align__(256) float g_obuf[NMAX * HID];
__device__ int g_is64_ei;
__device__ int g_is64_ty;

__device__ __forceinline__ long ldidx(const void* p, long i, int is64) {
    return is64 ? (long)((const long long*)p)[i] : (long)((const int*)p)[i];
}

// ---------------- packed f32x2 helpers ----------------
__device__ __forceinline__ ull pack2(float lo, float hi) {
    ull r; asm("mov.b64 %0, {%1, %2};" : "=l"(r) : "f"(lo), "f"(hi)); return r;
}
__device__ __forceinline__ void unpack2(ull v, float& lo, float& hi) {
    asm("mov.b64 {%0, %1}, %2;" : "=f"(lo), "=f"(hi) : "l"(v));
}
__device__ __forceinline__ void ffma2(ull& d, ull a, ull b) {
    asm("fma.rn.f32x2 %0, %1, %2, %0;" : "+l"(d) : "l"(a), "l"(b));
}
__device__ __forceinline__ ull mul2(ull a, ull b) {
    ull r; asm("mul.rn.f32x2 %0, %1, %2;" : "=l"(r) : "l"(a), "l"(b)); return r;
}

// ---------------- dtype detection ----------------
__global__ void detect_kernel(const unsigned* ei, const unsigned* ty) {
    if (threadIdx.x == 0) {
        unsigned a = 0;
        for (int i = 0; i < 32; i++) a |= ei[2 * i + 1];
        g_is64_ei = (a == 0) ? 1 : 0;
        unsigned b = 0;
        for (int i = 0; i < 32; i++) b |= ty[2 * i + 1];
        g_is64_ty = (b == 0) ? 1 : 0;
    }
}

__global__ void zero_kernel(int n) {
    int i = blockIdx.x * blockDim.x + threadIdx.x;
    if (i < n) g_agg[i] = 0.f;
}

// ---------------- P[n][d] = b1[d] + sum_{k<14} xe[n][k]*w1[d][k] ------------
__global__ void prep_kernel(const float* __restrict__ x, const float* __restrict__ emb,
                            const float* __restrict__ w1, const float* __restrict__ b1,
                            const void* __restrict__ ety) {
    int n = blockIdx.x, d = threadIdx.x;
    __shared__ float xs[14];
    int is64 = g_is64_ty;
    if (d < 6) {
        xs[d] = x[n * 6 + d];
    } else if (d < 14) {
        long t = ldidx(ety, n, is64);
        xs[d] = emb[t * 8 + (d - 6)];
    }
    __syncthreads();
    float acc = b1[d];
#pragma unroll
    for (int k = 0; k < 14; k++) acc = fmaf(xs[k], w1[d * 15 + k], acc);
    g_P[n * HID + d] = acc;
}

// ---------------- edge MLP + scatter-add: thread-per-edge -------------------
// 64 threads/block, each thread owns one edge. LayerNorms are in-thread.
// Layer-2 = packed f32x2 FMAs with warp-uniform (broadcast) smem weights.
__global__ void __launch_bounds__(64) edge_kernel(
    const void* __restrict__ ei, const float* __restrict__ eattr,
    const float* __restrict__ w1, const float* __restrict__ w2g,
    const float* __restrict__ b2g, const float* __restrict__ lng,
    const float* __restrict__ lnb, int nE) {
    __shared__ __align__(16) float w1ls[64];
    __shared__ __align__(16) float gs[64];
    __shared__ __align__(16) float bs[64];
    __shared__ __align__(16) float b2s[64];
    __shared__ __align__(16) float w2s[4096];
    __shared__ float h2col[64 * 64];   // column-major per-thread scratch

    int tid = threadIdx.x;
    w1ls[tid] = w1[tid * 15 + 14];
    gs[tid] = lng[tid];
    bs[tid] = lnb[tid];
    b2s[tid] = b2g[tid];
    for (int i = tid; i < 4096; i += 64) w2s[i] = w2g[i];
    __syncthreads();

    long e = (long)blockIdx.x * 64 + tid;
    bool act = e < nE;
    int is64 = g_is64_ei;
    long src = 0, dst = 0;
    float a = 0.f;
    if (act) {
        src = ldidx(ei, e, is64);
        dst = ldidx(ei, (long)nE + e, is64);
        a = eattr[e];
    }

    // ---- layer 1: pre = P[src] + a*w1_last, relu, in-thread stats ----
    float v[64];
    const float4* pr = (const float4*)(g_P + src * 64);
    float s1 = 0.f, q1 = 0.f;
#pragma unroll
    for (int g = 0; g < 16; g++) {
        float4 p = pr[g];
        float4 wl = ((const float4*)w1ls)[g];
        float x0 = fmaxf(fmaf(a, wl.x, p.x), 0.f);
        float x1 = fmaxf(fmaf(a, wl.y, p.y), 0.f);
        float x2 = fmaxf(fmaf(a, wl.z, p.z), 0.f);
        float x3 = fmaxf(fmaf(a, wl.w, p.w), 0.f);
        v[4 * g] = x0; v[4 * g + 1] = x1; v[4 * g + 2] = x2; v[4 * g + 3] = x3;
        s1 += (x0 + x1) + (x2 + x3);
        q1 = fmaf(x0, x0, q1); q1 = fmaf(x1, x1, q1);
        q1 = fmaf(x2, x2, q1); q1 = fmaf(x3, x3, q1);
    }
    float mean1 = s1 * (1.f / 64.f);
    float var1 = fmaf(-mean1, mean1, q1 * (1.f / 64.f));
    float r1 = rsqrtf(var1 + 1e-5f);
    float mr1 = -mean1 * r1;

    // ---- LN1 apply + pack to f32x2 pairs ----
    ull h1p[32];
#pragma unroll
    for (int g = 0; g < 16; g++) {
        float4 gg4 = ((const float4*)gs)[g];
        float4 bb4 = ((const float4*)bs)[g];
        float h0 = fmaf(fmaf(v[4 * g], r1, mr1), gg4.x, bb4.x);
        float h1 = fmaf(fmaf(v[4 * g + 1], r1, mr1), gg4.y, bb4.y);
        float h2 = fmaf(fmaf(v[4 * g + 2], r1, mr1), gg4.z, bb4.z);
        float h3 = fmaf(fmaf(v[4 * g + 3], r1, mr1), gg4.w, bb4.w);
        h1p[2 * g] = pack2(h0, h1);
        h1p[2 * g + 1] = pack2(h2, h3);
    }

    // ---- layer 2: 8 chunks of 8 outputs, f32x2 FMAs, broadcast weights ----
    const ulonglong2* w2p = (const ulonglong2*)w2s;
    float s2 = 0.f, q2 = 0.f;
    for (int c = 0; c < 8; c++) {
        ull acc[8];
#pragma unroll
        for (int j = 0; j < 8; j++) acc[j] = 0ull;
#pragma unroll 4
        for (int kp = 0; kp < 16; kp++) {
            ull ha = h1p[2 * kp], hb = h1p[2 * kp + 1];
#pragma unroll
            for (int j = 0; j < 8; j++) {
                ulonglong2 w = w2p[(c * 8 + j) * 16 + kp];
                ffma2(acc[j], w.x, ha);
                ffma2(acc[j], w.y, hb);
            }
        }
        float4 bq0 = ((const float4*)b2s)[2 * c];
        float4 bq1 = ((const float4*)b2s)[2 * c + 1];
        float bb[8] = {bq0.x, bq0.y, bq0.z, bq0.w, bq1.x, bq1.y, bq1.z, bq1.w};
#pragma unroll
        for (int j = 0; j < 8; j++) {
            float lo, hi;
            unpack2(acc[j], lo, hi);
            float val = fmaxf(bb[j] + (lo + hi), 0.f);
            s2 += val;
            q2 = fmaf(val, val, q2);
            h2col[(c * 8 + j) * 64 + tid] = val;
        }
    }
    float mean2 = s2 * (1.f / 64.f);
    float var2 = fmaf(-mean2, mean2, q2 * (1.f / 64.f));
    float r2 = rsqrtf(var2 + 1e-5f);
    float mr2 = -mean2 * r2;

    // ---- LN2 apply + vectorized scatter-add ----
    float* basep = g_agg + dst * 64;
#pragma unroll
    for (int g = 0; g < 16; g++) {
        float v0 = h2col[(4 * g + 0) * 64 + tid];
        float v1 = h2col[(4 * g + 1) * 64 + tid];
        float v2v = h2col[(4 * g + 2) * 64 + tid];
        float v3 = h2col[(4 * g + 3) * 64 + tid];
        float4 gg4 = ((const float4*)gs)[g];
        float4 bb4 = ((const float4*)bs)[g];
        float o0 = fmaf(fmaf(v0, r2, mr2), gg4.x, bb4.x);
        float o1 = fmaf(fmaf(v1, r2, mr2), gg4.y, bb4.y);
        float o2 = fmaf(fmaf(v2v, r2, mr2), gg4.z, bb4.z);
        float o3 = fmaf(fmaf(v3, r2, mr2), gg4.w, bb4.w);
        if (act) {
            asm volatile("red.global.add.v4.f32 [%0], {%1,%2,%3,%4};"
                         :: "l"(basep + 4 * g), "f"(o0), "f"(o1), "f"(o2), "f"(o3)
                         : "memory");
        }
    }
}

// ---------------- qkv = h @ in_proj_w.T + b -------------------------------
__global__ void __launch_bounds__(192) qkv_kernel(const float* __restrict__ w,
                                                  const float* __restrict__ b, int N) {
    __shared__ __align__(16) float hs[16 * 64];
    int tid = threadIdx.x;
    int n0 = blockIdx.x * 16;
    for (int i = tid; i < 16 * 64; i += 192) hs[i] = g_agg[n0 * 64 + i];
    float wr[64];
    {
        const float4* p4 = (const float4*)(w + tid * 64);
#pragma unroll
        for (int k = 0; k < 16; k++) {
            float4 f = p4[k];
            wr[4 * k] = f.x; wr[4 * k + 1] = f.y; wr[4 * k + 2] = f.z; wr[4 * k + 3] = f.w;
        }
    }
    float br = b[tid];
    __syncthreads();
    int sec = tid / 64, wi = tid % 64, hh = wi / 16, dd = wi % 16;
    float* dst = sec == 0 ? g_q : (sec == 1 ? g_k : g_v);
#pragma unroll 4
    for (int nn = 0; nn < 16; nn++) {
        float acc = br;
#pragma unroll
        for (int k = 0; k < 16; k++) {
            float4 h = *(const float4*)&hs[nn * 64 + 4 * k];
            acc = fmaf(wr[4 * k], h.x, acc);
            acc = fmaf(wr[4 * k + 1], h.y, acc);
            acc = fmaf(wr[4 * k + 2], h.z, acc);
            acc = fmaf(wr[4 * k + 3], h.w, acc);
        }
        dst[hh * N * 16 + (n0 + nn) * 16 + dd] = acc;
    }
}

// ---------------- flash attention, f32x2, 4-way K-split ---------------------
// Block = 128 thr = 32 queries x 4 K-quarters. grid = (N/32, 4 heads).
__global__ void __launch_bounds__(128) attn_kernel(int N) {
    int hh = blockIdx.y;
    int part = threadIdx.x >> 5;
    int lane = threadIdx.x & 31;
    int qi = blockIdx.x * 32 + lane;
    const float* Q = g_q + hh * N * 16;
    const float* K = g_k + hh * N * 16;
    const float* V = g_v + hh * N * 16;

    __shared__ __align__(16) float Ks[4][64 * 16];
    __shared__ __align__(16) float Vs[4][64 * 16];
    __shared__ float mrg[3][32][18];

    ull q2[8];
    {
        const float4* qp = (const float4*)(Q + qi * 16);
#pragma unroll
        for (int u = 0; u < 4; u++) {
            float4 f = qp[u];
            q2[2 * u] = pack2(f.x * 0.25f, f.y * 0.25f);
            q2[2 * u + 1] = pack2(f.z * 0.25f, f.w * 0.25f);
        }
    }
    ull o2[8];
#pragma unroll
    for (int u = 0; u < 8; u++) o2[u] = 0ull;
    float m = -1e30f, l = 0.f;

    int j0 = part * (N >> 2);
    for (int kt = 0; kt < (N >> 2); kt += 64) {
        {
            const float4* ksrc = (const float4*)(K + (j0 + kt) * 16);
            const float4* vsrc = (const float4*)(V + (j0 + kt) * 16);
            float4* kdst = (float4*)Ks[part];
            float4* vdst = (float4*)Vs[part];
#pragma unroll
            for (int u = 0; u < 8; u++) {
                kdst[u * 32 + lane] = ksrc[u * 32 + lane];
                vdst[u * 32 + lane] = vsrc[u * 32 + lane];
            }
        }
        __syncwarp();
#pragma unroll 2
        for (int j = 0; j < 64; j++) {
            const ulonglong2* kr = (const ulonglong2*)&Ks[part][j * 16];
            ulonglong2 ka = kr[0], kb = kr[1], kc = kr[2], kd = kr[3];
            ull s2 = mul2(q2[0], ka.x);
            ffma2(s2, q2[1], ka.y);
            ffma2(s2, q2[2], kb.x);
            ffma2(s2, q2[3], kb.y);
            ffma2(s2, q2[4], kc.x);
            ffma2(s2, q2[5], kc.y);
            ffma2(s2, q2[6], kd.x);
            ffma2(s2, q2[7], kd.y);
            float slo, shi;
            unpack2(s2, slo, shi);
            float s = slo + shi;
            float nm = fmaxf(m, s);
            float p = __expf(s - nm);
            if (nm > m) {
                float corr = __expf(m - nm);
                ull c2 = pack2(corr, corr);
                l *= corr;
#pragma unroll
                for (int u = 0; u < 8; u++) o2[u] = mul2(o2[u], c2);
                m = nm;
            }
            l += p;
            ull p2 = pack2(p, p);
            const ulonglong2* vr = (const ulonglong2*)&Vs[part][j * 16];
            ulonglong2 va = vr[0], vb = vr[1], vc = vr[2], vd = vr[3];
            ffma2(o2[0], p2, va.x);
            ffma2(o2[1], p2, va.y);
            ffma2(o2[2], p2, vb.x);
            ffma2(o2[3], p2, vb.y);
            ffma2(o2[4], p2, vc.x);
            ffma2(o2[5], p2, vc.y);
            ffma2(o2[6], p2, vd.x);
            ffma2(o2[7], p2, vd.y);
        }
        __syncwarp();
    }

    // ---- 4-way merge ----
    if (part != 0) {
        float* d = &mrg[part - 1][lane][0];
        d[0] = m;
        d[1] = l;
#pragma unroll
        for (int u = 0; u < 8; u++) {
            float lo, hi;
            unpack2(o2[u], lo, hi);
            d[2 + 2 * u] = lo;
            d[3 + 2 * u] = hi;
        }
    }
    __syncthreads();
    if (part == 0) {
        float M = m;
#pragma unroll
        for (int p2i = 0; p2i < 3; p2i++) M = fmaxf(M, mrg[p2i][lane][0]);
        float c0 = __expf(m - M);
        float L = l * c0;
        float o[16];
#pragma unroll
        for (int u = 0; u < 8; u++) {
            float lo, hi;
            unpack2(o2[u], lo, hi);
            o[2 * u] = lo * c0;
            o[2 * u + 1] = hi * c0;
        }
#pragma unroll
        for (int p2i = 0; p2i < 3; p2i++) {
            const float* sp = &mrg[p2i][lane][0];
            float cp = __expf(sp[0] - M);
            L = fmaf(sp[1], cp, L);
#pragma unroll
            for (int c = 0; c < 16; c++) o[c] = fmaf(sp[2 + c], cp, o[c]);
        }
        float inv = 1.f / L;
#pragma unroll
        for (int c = 0; c < 16; c++) g_obuf[qi * 64 + hh * 16 + c] = o[c] * inv;
    }
}

// ---------------- out_proj + residual + LN + final linear --------------------
__global__ void __launch_bounds__(64) epi_kernel(
    const float* __restrict__ opw, const float* __restrict__ opb,
    const float* __restrict__ ang, const float* __restrict__ anb,
    const float* __restrict__ ow, const float* __restrict__ ob,
    float* __restrict__ out) {
    int d = threadIdx.x;
    int n0 = blockIdx.x * 8;
    __shared__ __align__(16) float os[8 * 64];
    __shared__ __align__(16) float ts[8 * 64];
    __shared__ float ps[8][8], pq[8][8];
    __shared__ float mv[8][2];

    for (int i = d; i < 8 * 64; i += 64) os[i] = g_obuf[n0 * 64 + i];
    float wr[64];
    {
        const float4* p4 = (const float4*)(opw + d * 64);
#pragma unroll
        for (int k = 0; k < 16; k++) {
            float4 f = p4[k];
            wr[4 * k] = f.x; wr[4 * k + 1] = f.y; wr[4 * k + 2] = f.z; wr[4 * k + 3] = f.w;
        }
    }
    float bb = opb[d];
    __syncthreads();
#pragma unroll
    for (int nn = 0; nn < 8; nn++) {
        float acc = bb;
#pragma unroll
        for (int k = 0; k < 16; k++) {
            float4 h = *(const float4*)&os[nn * 64 + 4 * k];
            acc = fmaf(wr[4 * k], h.x, acc);
            acc = fmaf(wr[4 * k + 1], h.y, acc);
            acc = fmaf(wr[4 * k + 2], h.z, acc);
            acc = fmaf(wr[4 * k + 3], h.w, acc);
        }
        ts[nn * 64 + d] = g_agg[(n0 + nn) * 64 + d] + acc;
    }
    __syncthreads();
    {
        int n = d >> 3, sg = d & 7;
        float s = 0.f, qq = 0.f;
#pragma unroll
        for (int t = 0; t < 8; t++) {
            float v2 = ts[n * 64 + sg * 8 + t];
            s += v2; qq += v2 * v2;
        }
        ps[n][sg] = s; pq[n][sg] = qq;
    }
    __syncthreads();
    if (d < 8) {
        float s = 0.f, qq = 0.f;
#pragma unroll
        for (int t = 0; t < 8; t++) { s += ps[d][t]; qq += pq[d][t]; }
        float mean = s * (1.f / 64.f);
        float var = qq * (1.f / 64.f) - mean * mean;
        mv[d][0] = mean;
        mv[d][1] = rsqrtf(var + 1e-5f);
    }
    __syncthreads();
    float gg = ang[d], gb = anb[d];
#pragma unroll
    for (int nn = 0; nn < 8; nn++)
        ts[nn * 64 + d] = (ts[nn * 64 + d] - mv[nn][0]) * mv[nn][1] * gg + gb;
    {
        const float4* p4 = (const float4*)(ow + d * 64);
#pragma unroll
        for (int k = 0; k < 16; k++) {
            float4 f = p4[k];
            wr[4 * k] = f.x; wr[4 * k + 1] = f.y; wr[4 * k + 2] = f.z; wr[4 * k + 3] = f.w;
        }
    }
    float bo = ob[d];
    __syncthreads();
#pragma unroll
    for (int nn = 0; nn < 8; nn++) {
        float acc = bo;
#pragma unroll
        for (int k = 0; k < 16; k++) {
            float4 h = *(const float4*)&ts[nn * 64 + 4 * k];
            acc = fmaf(wr[4 * k], h.x, acc);
            acc = fmaf(wr[4 * k + 1], h.y, acc);
            acc = fmaf(wr[4 * k + 2], h.z, acc);
            acc = fmaf(wr[4 * k + 3], h.w, acc);
        }
        out[(n0 + nn) * 64 + d] = acc;
    }
}

// ---------------- launch ----------------
extern "C" void kernel_launch(void* const* d_in, const int* in_sizes, int n_in,
                              void* d_out, int out_size) {
    const float* x        = (const float*)d_in[0];
    const float* eattr    = (const float*)d_in[1];
    const float* emb      = (const float*)d_in[2];
    const float* lin1_w   = (const float*)d_in[3];
    const float* lin1_b   = (const float*)d_in[4];
    const float* lay_w    = (const float*)d_in[5];
    const float* lay_b    = (const float*)d_in[6];
    const float* ln_g     = (const float*)d_in[7];
    const float* ln_b     = (const float*)d_in[8];
    const float* in_proj_w  = (const float*)d_in[9];
    const float* in_proj_b  = (const float*)d_in[10];
    const float* out_proj_w = (const float*)d_in[11];
    const float* out_proj_b = (const float*)d_in[12];
    const float* an_g     = (const float*)d_in[13];
    const float* an_b     = (const float*)d_in[14];
    const float* out_w    = (const float*)d_in[15];
    const float* out_b    = (const float*)d_in[16];
    const void*  ei       = d_in[17];
    const void*  ety      = d_in[18];

    int E = in_sizes[1];
    int N = in_sizes[0] / 6;

    detect_kernel<<<1, 32>>>((const unsigned*)ei, (const unsigned*)ety);
    zero_kernel<<<(N * HID + 255) / 256, 256>>>(N * HID);
    prep_kernel<<<N, 64>>>(x, emb, lin1_w, lin1_b, ety);
    edge_kernel<<<(E + 63) / 64, 64>>>(ei, eattr, lin1_w, lay_w, lay_b, ln_g, ln_b, E);
    qkv_kernel<<<N / 16, 192>>>(in_proj_w, in_proj_b, N);
    attn_kernel<<<dim3(N / 32, 4), 128>>>(N);
    epi_kernel<<<N / 8, 64>>>(out_proj_w, out_proj_b, an_g, an_b, out_w, out_b,
                              (float*)d_out);
}

// round 3
// speedup vs baseline: 1.3332x; 1.0015x over previous
#include <cuda_runtime.h>
#include <cstdint>

#define NMAX 4096
#define HID 64

typedef unsigned long long ull;

// ---------------- device scratch ----------------
__device__ __align__(256) float g_P[NMAX * HID];
__device__ __align__(256) float g_agg[NMAX * HID];
__device__ __align__(256) float g_q[4 * NMAX * 16];
__device__ __align__(256) float g_k[4 * NMAX * 16];
__device__ __align__(256) float g_v[4 * NMAX * 16];
__device__ __align__(256) float g_obuf[NMAX * HID];
__device__ int g_is64_ei;
__device__ int g_is64_ty;

__device__ __forceinline__ long ldidx(const void* p, long i, int is64) {
    return is64 ? (long)((const long long*)p)[i] : (long)((const int*)p)[i];
}

// ---------------- packed f32x2 helpers ----------------
__device__ __forceinline__ ull pack2(float lo, float hi) {
    ull r; asm("mov.b64 %0, {%1, %2};" : "=l"(r) : "f"(lo), "f"(hi)); return r;
}
__device__ __forceinline__ void unpack2(ull v, float& lo, float& hi) {
    asm("mov.b64 {%0, %1}, %2;" : "=f"(lo), "=f"(hi) : "l"(v));
}
__device__ __forceinline__ void ffma2(ull& d, ull a, ull b) {
    asm("fma.rn.f32x2 %0, %1, %2, %0;" : "+l"(d) : "l"(a), "l"(b));
}
__device__ __forceinline__ ull mul2(ull a, ull b) {
    ull r; asm("mul.rn.f32x2 %0, %1, %2;" : "=l"(r) : "l"(a), "l"(b)); return r;
}

// ---------------- dtype detection ----------------
__global__ void detect_kernel(const unsigned* ei, const unsigned* ty) {
    if (threadIdx.x == 0) {
        unsigned a = 0;
        for (int i = 0; i < 32; i++) a |= ei[2 * i + 1];
        g_is64_ei = (a == 0) ? 1 : 0;
        unsigned b = 0;
        for (int i = 0; i < 32; i++) b |= ty[2 * i + 1];
        g_is64_ty = (b == 0) ? 1 : 0;
    }
}

__global__ void zero_kernel(int n) {
    int i = blockIdx.x * blockDim.x + threadIdx.x;
    if (i < n) g_agg[i] = 0.f;
}

// ---------------- P[n][d] = b1[d] + sum_{k<14} xe[n][k]*w1[d][k] ------------
__global__ void prep_kernel(const float* __restrict__ x, const float* __restrict__ emb,
                            const float* __restrict__ w1, const float* __restrict__ b1,
                            const void* __restrict__ ety) {
    int n = blockIdx.x, d = threadIdx.x;
    __shared__ float xs[14];
    int is64 = g_is64_ty;
    if (d < 6) {
        xs[d] = x[n * 6 + d];
    } else if (d < 14) {
        long t = ldidx(ety, n, is64);
        xs[d] = emb[t * 8 + (d - 6)];
    }
    __syncthreads();
    float acc = b1[d];
#pragma unroll
    for (int k = 0; k < 14; k++) acc = fmaf(xs[k], w1[d * 15 + k], acc);
    g_P[n * HID + d] = acc;
}

// ---------------- edge MLP + scatter-add: thread-per-edge -------------------
// 64 threads/block, each thread owns one edge. LayerNorms are in-thread.
// Layer-2 = packed f32x2 FMAs with warp-uniform (broadcast) smem weights.
__global__ void __launch_bounds__(64) edge_kernel(
    const void* __restrict__ ei, const float* __restrict__ eattr,
    const float* __restrict__ w1, const float* __restrict__ w2g,
    const float* __restrict__ b2g, const float* __restrict__ lng,
    const float* __restrict__ lnb, int nE) {
    __shared__ __align__(16) float w1ls[64];
    __shared__ __align__(16) float gs[64];
    __shared__ __align__(16) float bs[64];
    __shared__ __align__(16) float b2s[64];
    __shared__ __align__(16) float w2s[4096];
    __shared__ float h2col[64 * 64];   // column-major per-thread scratch

    int tid = threadIdx.x;
    w1ls[tid] = w1[tid * 15 + 14];
    gs[tid] = lng[tid];
    bs[tid] = lnb[tid];
    b2s[tid] = b2g[tid];
    for (int i = tid; i < 4096; i += 64) w2s[i] = w2g[i];
    __syncthreads();

    long e = (long)blockIdx.x * 64 + tid;
    bool act = e < nE;
    int is64 = g_is64_ei;
    long src = 0, dst = 0;
    float a = 0.f;
    if (act) {
        src = ldidx(ei, e, is64);
        dst = ldidx(ei, (long)nE + e, is64);
        a = eattr[e];
    }

    // ---- layer 1: pre = P[src] + a*w1_last, relu, in-thread stats ----
    float v[64];
    const float4* pr = (const float4*)(g_P + src * 64);
    float s1 = 0.f, q1 = 0.f;
#pragma unroll
    for (int g = 0; g < 16; g++) {
        float4 p = pr[g];
        float4 wl = ((const float4*)w1ls)[g];
        float x0 = fmaxf(fmaf(a, wl.x, p.x), 0.f);
        float x1 = fmaxf(fmaf(a, wl.y, p.y), 0.f);
        float x2 = fmaxf(fmaf(a, wl.z, p.z), 0.f);
        float x3 = fmaxf(fmaf(a, wl.w, p.w), 0.f);
        v[4 * g] = x0; v[4 * g + 1] = x1; v[4 * g + 2] = x2; v[4 * g + 3] = x3;
        s1 += (x0 + x1) + (x2 + x3);
        q1 = fmaf(x0, x0, q1); q1 = fmaf(x1, x1, q1);
        q1 = fmaf(x2, x2, q1); q1 = fmaf(x3, x3, q1);
    }
    float mean1 = s1 * (1.f / 64.f);
    float var1 = fmaf(-mean1, mean1, q1 * (1.f / 64.f));
    float r1 = rsqrtf(var1 + 1e-5f);
    float mr1 = -mean1 * r1;

    // ---- LN1 apply + pack to f32x2 pairs ----
    ull h1p[32];
#pragma unroll
    for (int g = 0; g < 16; g++) {
        float4 gg4 = ((const float4*)gs)[g];
        float4 bb4 = ((const float4*)bs)[g];
        float h0 = fmaf(fmaf(v[4 * g], r1, mr1), gg4.x, bb4.x);
        float h1 = fmaf(fmaf(v[4 * g + 1], r1, mr1), gg4.y, bb4.y);
        float h2 = fmaf(fmaf(v[4 * g + 2], r1, mr1), gg4.z, bb4.z);
        float h3 = fmaf(fmaf(v[4 * g + 3], r1, mr1), gg4.w, bb4.w);
        h1p[2 * g] = pack2(h0, h1);
        h1p[2 * g + 1] = pack2(h2, h3);
    }

    // ---- layer 2: 8 chunks of 8 outputs, f32x2 FMAs, broadcast weights ----
    const ulonglong2* w2p = (const ulonglong2*)w2s;
    float s2 = 0.f, q2 = 0.f;
    for (int c = 0; c < 8; c++) {
        ull acc[8];
#pragma unroll
        for (int j = 0; j < 8; j++) acc[j] = 0ull;
#pragma unroll 4
        for (int kp = 0; kp < 16; kp++) {
            ull ha = h1p[2 * kp], hb = h1p[2 * kp + 1];
#pragma unroll
            for (int j = 0; j < 8; j++) {
                ulonglong2 w = w2p[(c * 8 + j) * 16 + kp];
                ffma2(acc[j], w.x, ha);
                ffma2(acc[j], w.y, hb);
            }
        }
        float4 bq0 = ((const float4*)b2s)[2 * c];
        float4 bq1 = ((const float4*)b2s)[2 * c + 1];
        float bb[8] = {bq0.x, bq0.y, bq0.z, bq0.w, bq1.x, bq1.y, bq1.z, bq1.w};
#pragma unroll
        for (int j = 0; j < 8; j++) {
            float lo, hi;
            unpack2(acc[j], lo, hi);
            float val = fmaxf(bb[j] + (lo + hi), 0.f);
            s2 += val;
            q2 = fmaf(val, val, q2);
            h2col[(c * 8 + j) * 64 + tid] = val;
        }
    }
    float mean2 = s2 * (1.f / 64.f);
    float var2 = fmaf(-mean2, mean2, q2 * (1.f / 64.f));
    float r2 = rsqrtf(var2 + 1e-5f);
    float mr2 = -mean2 * r2;

    // ---- LN2 apply + vectorized scatter-add ----
    float* basep = g_agg + dst * 64;
#pragma unroll
    for (int g = 0; g < 16; g++) {
        float v0 = h2col[(4 * g + 0) * 64 + tid];
        float v1 = h2col[(4 * g + 1) * 64 + tid];
        float v2v = h2col[(4 * g + 2) * 64 + tid];
        float v3 = h2col[(4 * g + 3) * 64 + tid];
        float4 gg4 = ((const float4*)gs)[g];
        float4 bb4 = ((const float4*)bs)[g];
        float o0 = fmaf(fmaf(v0, r2, mr2), gg4.x, bb4.x);
        float o1 = fmaf(fmaf(v1, r2, mr2), gg4.y, bb4.y);
        float o2 = fmaf(fmaf(v2v, r2, mr2), gg4.z, bb4.z);
        float o3 = fmaf(fmaf(v3, r2, mr2), gg4.w, bb4.w);
        if (act) {
            asm volatile("red.global.add.v4.f32 [%0], {%1,%2,%3,%4};"
                         :: "l"(basep + 4 * g), "f"(o0), "f"(o1), "f"(o2), "f"(o3)
                         : "memory");
        }
    }
}

// ---------------- qkv = h @ in_proj_w.T + b -------------------------------
__global__ void __launch_bounds__(192) qkv_kernel(const float* __restrict__ w,
                                                  const float* __restrict__ b, int N) {
    __shared__ __align__(16) float hs[16 * 64];
    int tid = threadIdx.x;
    int n0 = blockIdx.x * 16;
    for (int i = tid; i < 16 * 64; i += 192) hs[i] = g_agg[n0 * 64 + i];
    float wr[64];
    {
        const float4* p4 = (const float4*)(w + tid * 64);
#pragma unroll
        for (int k = 0; k < 16; k++) {
            float4 f = p4[k];
            wr[4 * k] = f.x; wr[4 * k + 1] = f.y; wr[4 * k + 2] = f.z; wr[4 * k + 3] = f.w;
        }
    }
    float br = b[tid];
    __syncthreads();
    int sec = tid / 64, wi = tid % 64, hh = wi / 16, dd = wi % 16;
    float* dst = sec == 0 ? g_q : (sec == 1 ? g_k : g_v);
#pragma unroll 4
    for (int nn = 0; nn < 16; nn++) {
        float acc = br;
#pragma unroll
        for (int k = 0; k < 16; k++) {
            float4 h = *(const float4*)&hs[nn * 64 + 4 * k];
            acc = fmaf(wr[4 * k], h.x, acc);
            acc = fmaf(wr[4 * k + 1], h.y, acc);
            acc = fmaf(wr[4 * k + 2], h.z, acc);
            acc = fmaf(wr[4 * k + 3], h.w, acc);
        }
        dst[hh * N * 16 + (n0 + nn) * 16 + dd] = acc;
    }
}

// ---------------- flash attention, f32x2, 4-way K-split ---------------------
// Block = 128 thr = 32 queries x 4 K-quarters. grid = (N/32, 4 heads).
__global__ void __launch_bounds__(128) attn_kernel(int N) {
    int hh = blockIdx.y;
    int part = threadIdx.x >> 5;
    int lane = threadIdx.x & 31;
    int qi = blockIdx.x * 32 + lane;
    const float* Q = g_q + hh * N * 16;
    const float* K = g_k + hh * N * 16;
    const float* V = g_v + hh * N * 16;

    __shared__ __align__(16) float Ks[4][64 * 16];
    __shared__ __align__(16) float Vs[4][64 * 16];
    __shared__ float mrg[3][32][18];

    ull q2[8];
    {
        const float4* qp = (const float4*)(Q + qi * 16);
#pragma unroll
        for (int u = 0; u < 4; u++) {
            float4 f = qp[u];
            q2[2 * u] = pack2(f.x * 0.25f, f.y * 0.25f);
            q2[2 * u + 1] = pack2(f.z * 0.25f, f.w * 0.25f);
        }
    }
    ull o2[8];
#pragma unroll
    for (int u = 0; u < 8; u++) o2[u] = 0ull;
    float m = -1e30f, l = 0.f;

    int j0 = part * (N >> 2);
    for (int kt = 0; kt < (N >> 2); kt += 64) {
        {
            const float4* ksrc = (const float4*)(K + (j0 + kt) * 16);
            const float4* vsrc = (const float4*)(V + (j0 + kt) * 16);
            float4* kdst = (float4*)Ks[part];
            float4* vdst = (float4*)Vs[part];
#pragma unroll
            for (int u = 0; u < 8; u++) {
                kdst[u * 32 + lane] = ksrc[u * 32 + lane];
                vdst[u * 32 + lane] = vsrc[u * 32 + lane];
            }
        }
        __syncwarp();
#pragma unroll 2
        for (int j = 0; j < 64; j++) {
            const ulonglong2* kr = (const ulonglong2*)&Ks[part][j * 16];
            ulonglong2 ka = kr[0], kb = kr[1], kc = kr[2], kd = kr[3];
            ull s2 = mul2(q2[0], ka.x);
            ffma2(s2, q2[1], ka.y);
            ffma2(s2, q2[2], kb.x);
            ffma2(s2, q2[3], kb.y);
            ffma2(s2, q2[4], kc.x);
            ffma2(s2, q2[5], kc.y);
            ffma2(s2, q2[6], kd.x);
            ffma2(s2, q2[7], kd.y);
            float slo, shi;
            unpack2(s2, slo, shi);
            float s = slo + shi;
            float nm = fmaxf(m, s);
            float p = __expf(s - nm);
            if (nm > m) {
                float corr = __expf(m - nm);
                ull c2 = pack2(corr, corr);
                l *= corr;
#pragma unroll
                for (int u = 0; u < 8; u++) o2[u] = mul2(o2[u], c2);
                m = nm;
            }
            l += p;
            ull p2 = pack2(p, p);
            const ulonglong2* vr = (const ulonglong2*)&Vs[part][j * 16];
            ulonglong2 va = vr[0], vb = vr[1], vc = vr[2], vd = vr[3];
            ffma2(o2[0], p2, va.x);
            ffma2(o2[1], p2, va.y);
            ffma2(o2[2], p2, vb.x);
            ffma2(o2[3], p2, vb.y);
            ffma2(o2[4], p2, vc.x);
            ffma2(o2[5], p2, vc.y);
            ffma2(o2[6], p2, vd.x);
            ffma2(o2[7], p2, vd.y);
        }
        __syncwarp();
    }

    // ---- 4-way merge ----
    if (part != 0) {
        float* d = &mrg[part - 1][lane][0];
        d[0] = m;
        d[1] = l;
#pragma unroll
        for (int u = 0; u < 8; u++) {
            float lo, hi;
            unpack2(o2[u], lo, hi);
            d[2 + 2 * u] = lo;
            d[3 + 2 * u] = hi;
        }
    }
    __syncthreads();
    if (part == 0) {
        float M = m;
#pragma unroll
        for (int p2i = 0; p2i < 3; p2i++) M = fmaxf(M, mrg[p2i][lane][0]);
        float c0 = __expf(m - M);
        float L = l * c0;
        float o[16];
#pragma unroll
        for (int u = 0; u < 8; u++) {
            float lo, hi;
            unpack2(o2[u], lo, hi);
            o[2 * u] = lo * c0;
            o[2 * u + 1] = hi * c0;
        }
#pragma unroll
        for (int p2i = 0; p2i < 3; p2i++) {
            const float* sp = &mrg[p2i][lane][0];
            float cp = __expf(sp[0] - M);
            L = fmaf(sp[1], cp, L);
#pragma unroll
            for (int c = 0; c < 16; c++) o[c] = fmaf(sp[2 + c], cp, o[c]);
        }
        float inv = 1.f / L;
#pragma unroll
        for (int c = 0; c < 16; c++) g_obuf[qi * 64 + hh * 16 + c] = o[c] * inv;
    }
}

// ---------------- out_proj + residual + LN + final linear --------------------
__global__ void __launch_bounds__(64) epi_kernel(
    const float* __restrict__ opw, const float* __restrict__ opb,
    const float* __restrict__ ang, const float* __restrict__ anb,
    const float* __restrict__ ow, const float* __restrict__ ob,
    float* __restrict__ out) {
    int d = threadIdx.x;
    int n0 = blockIdx.x * 8;
    __shared__ __align__(16) float os[8 * 64];
    __shared__ __align__(16) float ts[8 * 64];
    __shared__ float ps[8][8], pq[8][8];
    __shared__ float mv[8][2];

    for (int i = d; i < 8 * 64; i += 64) os[i] = g_obuf[n0 * 64 + i];
    float wr[64];
    {
        const float4* p4 = (const float4*)(opw + d * 64);
#pragma unroll
        for (int k = 0; k < 16; k++) {
            float4 f = p4[k];
            wr[4 * k] = f.x; wr[4 * k + 1] = f.y; wr[4 * k + 2] = f.z; wr[4 * k + 3] = f.w;
        }
    }
    float bb = opb[d];
    __syncthreads();
#pragma unroll
    for (int nn = 0; nn < 8; nn++) {
        float acc = bb;
#pragma unroll
        for (int k = 0; k < 16; k++) {
            float4 h = *(const float4*)&os[nn * 64 + 4 * k];
            acc = fmaf(wr[4 * k], h.x, acc);
            acc = fmaf(wr[4 * k + 1], h.y, acc);
            acc = fmaf(wr[4 * k + 2], h.z, acc);
            acc = fmaf(wr[4 * k + 3], h.w, acc);
        }
        ts[nn * 64 + d] = g_agg[(n0 + nn) * 64 + d] + acc;
    }
    __syncthreads();
    {
        int n = d >> 3, sg = d & 7;
        float s = 0.f, qq = 0.f;
#pragma unroll
        for (int t = 0; t < 8; t++) {
            float v2 = ts[n * 64 + sg * 8 + t];
            s += v2; qq += v2 * v2;
        }
        ps[n][sg] = s; pq[n][sg] = qq;
    }
    __syncthreads();
    if (d < 8) {
        float s = 0.f, qq = 0.f;
#pragma unroll
        for (int t = 0; t < 8; t++) { s += ps[d][t]; qq += pq[d][t]; }
        float mean = s * (1.f / 64.f);
        float var = qq * (1.f / 64.f) - mean * mean;
        mv[d][0] = mean;
        mv[d][1] = rsqrtf(var + 1e-5f);
    }
    __syncthreads();
    float gg = ang[d], gb = anb[d];
#pragma unroll
    for (int nn = 0; nn < 8; nn++)
        ts[nn * 64 + d] = (ts[nn * 64 + d] - mv[nn][0]) * mv[nn][1] * gg + gb;
    {
        const float4* p4 = (const float4*)(ow + d * 64);
#pragma unroll
        for (int k = 0; k < 16; k++) {
            float4 f = p4[k];
            wr[4 * k] = f.x; wr[4 * k + 1] = f.y; wr[4 * k + 2] = f.z; wr[4 * k + 3] = f.w;
        }
    }
    float bo = ob[d];
    __syncthreads();
#pragma unroll
    for (int nn = 0; nn < 8; nn++) {
        float acc = bo;
#pragma unroll
        for (int k = 0; k < 16; k++) {
            float4 h = *(const float4*)&ts[nn * 64 + 4 * k];
            acc = fmaf(wr[4 * k], h.x, acc);
            acc = fmaf(wr[4 * k + 1], h.y, acc);
            acc = fmaf(wr[4 * k + 2], h.z, acc);
            acc = fmaf(wr[4 * k + 3], h.w, acc);
        }
        out[(n0 + nn) * 64 + d] = acc;
    }
}

// ---------------- launch ----------------
extern "C" void kernel_launch(void* const* d_in, const int* in_sizes, int n_in,
                              void* d_out, int out_size) {
    const float* x        = (const float*)d_in[0];
    const float* eattr    = (const float*)d_in[1];
    const float* emb      = (const float*)d_in[2];
    const float* lin1_w   = (const float*)d_in[3];
    const float* lin1_b   = (const float*)d_in[4];
    const float* lay_w    = (const float*)d_in[5];
    const float* lay_b    = (const float*)d_in[6];
    const float* ln_g     = (const float*)d_in[7];
    const float* ln_b     = (const float*)d_in[8];
    const float* in_proj_w  = (const float*)d_in[9];
    const float* in_proj_b  = (const float*)d_in[10];
    const float* out_proj_w = (const float*)d_in[11];
    const float* out_proj_b = (const float*)d_in[12];
    const float* an_g     = (const float*)d_in[13];
    const float* an_b     = (const float*)d_in[14];
    const float* out_w    = (const float*)d_in[15];
    const float* out_b    = (const float*)d_in[16];
    const void*  ei       = d_in[17];
    const void*  ety      = d_in[18];

    int E = in_sizes[1];
    int N = in_sizes[0] / 6;

    detect_kernel<<<1, 32>>>((const unsigned*)ei, (const unsigned*)ety);
    zero_kernel<<<(N * HID + 255) / 256, 256>>>(N * HID);
    prep_kernel<<<N, 64>>>(x, emb, lin1_w, lin1_b, ety);
    edge_kernel<<<(E + 63) / 64, 64>>>(ei, eattr, lin1_w, lay_w, lay_b, ln_g, ln_b, E);
    qkv_kernel<<<N / 16, 192>>>(in_proj_w, in_proj_b, N);
    attn_kernel<<<dim3(N / 32, 4), 128>>>(N);
    epi_kernel<<<N / 8, 64>>>(out_proj_w, out_proj_b, an_g, an_b, out_w, out_b,
                              (float*)d_out);
}

// round 4
// speedup vs baseline: 1.6137x; 1.2104x over previous
#include <cuda_runtime.h>
#include <cstdint>

#define NMAX 4096
#define HID 64

typedef unsigned long long ull;

// ---------------- device scratch ----------------
__device__ __align__(256) float g_P[NMAX * HID];
__device__ __align__(256) float g_agg[NMAX * HID];
__device__ __align__(256) float g_q[4 * NMAX * 16];
__device__ __align__(256) float g_k[4 * NMAX * 16];
__device__ __align__(256) float g_v[4 * NMAX * 16];
__device__ __align__(256) float g_obuf[NMAX * HID];
__device__ __align__(256) ull g_w2dup[64 * 64];   // [k][d] = pack2(w2[d][k], w2[d][k])
__device__ int g_is64_ei;
__device__ int g_is64_ty;

__device__ __forceinline__ long ldidx(const void* p, long i, int is64) {
    return is64 ? (long)((const long long*)p)[i] : (long)((const int*)p)[i];
}

// ---------------- packed f32x2 helpers ----------------
__device__ __forceinline__ ull pack2(float lo, float hi) {
    ull r; asm("mov.b64 %0, {%1, %2};" : "=l"(r) : "f"(lo), "f"(hi)); return r;
}
__device__ __forceinline__ void unpack2(ull v, float& lo, float& hi) {
    asm("mov.b64 {%0, %1}, %2;" : "=f"(lo), "=f"(hi) : "l"(v));
}
__device__ __forceinline__ void ffma2(ull& d, ull a, ull b) {
    asm("fma.rn.f32x2 %0, %1, %2, %0;" : "+l"(d) : "l"(a), "l"(b));
}
__device__ __forceinline__ ull mul2(ull a, ull b) {
    ull r; asm("mul.rn.f32x2 %0, %1, %2;" : "=l"(r) : "l"(a), "l"(b)); return r;
}

// ---------------- dtype detection ----------------
__global__ void detect_kernel(const unsigned* ei, const unsigned* ty) {
    if (threadIdx.x == 0) {
        unsigned a = 0;
        for (int i = 0; i < 32; i++) a |= ei[2 * i + 1];
        g_is64_ei = (a == 0) ? 1 : 0;
        unsigned b = 0;
        for (int i = 0; i < 32; i++) b |= ty[2 * i + 1];
        g_is64_ty = (b == 0) ? 1 : 0;
    }
}

__global__ void zero_kernel(int n) {
    int i = blockIdx.x * blockDim.x + threadIdx.x;
    if (i < n) g_agg[i] = 0.f;
}

// ---------------- duplicate-pack layer-2 weights, k-major -------------------
__global__ void packw_kernel(const float* __restrict__ w2g) {
    int i = blockIdx.x * blockDim.x + threadIdx.x;   // 4096
    int k = i >> 6, d = i & 63;
    float w = w2g[d * 64 + k];
    g_w2dup[k * 64 + d] = pack2(w, w);
}

// ---------------- P[n][d] = b1[d] + sum_{k<14} xe[n][k]*w1[d][k] ------------
__global__ void prep_kernel(const float* __restrict__ x, const float* __restrict__ emb,
                            const float* __restrict__ w1, const float* __restrict__ b1,
                            const void* __restrict__ ety) {
    int n = blockIdx.x, d = threadIdx.x;
    __shared__ float xs[14];
    int is64 = g_is64_ty;
    if (d < 6) {
        xs[d] = x[n * 6 + d];
    } else if (d < 14) {
        long t = ldidx(ety, n, is64);
        xs[d] = emb[t * 8 + (d - 6)];
    }
    __syncthreads();
    float acc = b1[d];
#pragma unroll
    for (int k = 0; k < 14; k++) acc = fmaf(xs[k], w1[d * 15 + k], acc);
    g_P[n * HID + d] = acc;
}

// ---------------- edge MLP + scatter-add: GEMM-structured -------------------
// 128 threads, 128 edges per block. Stage A: thread-per-edge h1+LN1 -> smem
// k-major. Stage B: register-tiled 128x64x64 GEMM (8 edges x 8 dims / thread,
// f32x2 with pre-duplicated weights). Stage C: LN2 via smem partials + red.
#define EDGE_SMEM (32768 + 32768 + 1024 + 512)
__global__ void __launch_bounds__(128) edge_kernel(
    const void* __restrict__ ei, const float* __restrict__ eattr,
    const float* __restrict__ w1, const float* __restrict__ b2g,
    const float* __restrict__ lng, const float* __restrict__ lnb, int nE) {
    extern __shared__ __align__(16) char smem_raw[];
    ull* h1s2 = (ull*)smem_raw;                         // 4096 ull = 32KB  [k][epair]
    float* h1f = (float*)smem_raw;                      // same region, [k][128]
    ull* w2s = (ull*)(smem_raw + 32768);                // 4096 ull = 32KB  [k][d] dup
    float* gs = (float*)(smem_raw + 65536);             // 64
    float* bs = gs + 64;                                // 64
    float* w1ls = bs + 64;                              // 64
    float* b2v = w1ls + 64;                             // 64
    int* sdst = (int*)(b2v + 64);                       // 128
    // overlays into h1s2 region (valid after GEMM, post-sync):
    float* ps = (float*)smem_raw;                       // 8*128
    float* pq = ps + 1024;                              // 8*128
    float* st2 = pq + 1024;                             // 128*2

    int tid = threadIdx.x;
    {
        const ull* wsrc = g_w2dup;
        for (int i = tid; i < 4096; i += 128) w2s[i] = wsrc[i];
        if (tid < 64) {
            gs[tid] = lng[tid];
            bs[tid] = lnb[tid];
            w1ls[tid] = w1[tid * 15 + 14];
            b2v[tid] = b2g[tid];
        }
    }

    long e = (long)blockIdx.x * 128 + tid;
    bool act = e < nE;
    int is64 = g_is64_ei;
    long src = 0;
    float a = 0.f;
    {
        long dstl = -1;
        if (act) {
            src = ldidx(ei, e, is64);
            dstl = ldidx(ei, (long)nE + e, is64);
            a = eattr[e];
        }
        sdst[tid] = (int)dstl;
    }
    __syncthreads();

    // ---- Stage A: layer 1 + LN1, in-thread ----
    {
        float v[64];
        const float4* pr = (const float4*)(g_P + src * 64);
        float s1 = 0.f, q1 = 0.f;
#pragma unroll
        for (int g = 0; g < 16; g++) {
            float4 p = pr[g];
            float4 wl = ((const float4*)w1ls)[g];
            float x0 = fmaxf(fmaf(a, wl.x, p.x), 0.f);
            float x1 = fmaxf(fmaf(a, wl.y, p.y), 0.f);
            float x2 = fmaxf(fmaf(a, wl.z, p.z), 0.f);
            float x3 = fmaxf(fmaf(a, wl.w, p.w), 0.f);
            v[4 * g] = x0; v[4 * g + 1] = x1; v[4 * g + 2] = x2; v[4 * g + 3] = x3;
            s1 += (x0 + x1) + (x2 + x3);
            q1 = fmaf(x0, x0, q1); q1 = fmaf(x1, x1, q1);
            q1 = fmaf(x2, x2, q1); q1 = fmaf(x3, x3, q1);
        }
        float mean1 = s1 * (1.f / 64.f);
        float var1 = fmaf(-mean1, mean1, q1 * (1.f / 64.f));
        float r1 = rsqrtf(var1 + 1e-5f);
        float mr1 = -mean1 * r1;
#pragma unroll
        for (int g = 0; g < 16; g++) {
            float4 gg4 = ((const float4*)gs)[g];
            float4 bb4 = ((const float4*)bs)[g];
            h1f[(4 * g + 0) * 128 + tid] = fmaf(fmaf(v[4 * g], r1, mr1), gg4.x, bb4.x);
            h1f[(4 * g + 1) * 128 + tid] = fmaf(fmaf(v[4 * g + 1], r1, mr1), gg4.y, bb4.y);
            h1f[(4 * g + 2) * 128 + tid] = fmaf(fmaf(v[4 * g + 2], r1, mr1), gg4.z, bb4.z);
            h1f[(4 * g + 3) * 128 + tid] = fmaf(fmaf(v[4 * g + 3], r1, mr1), gg4.w, bb4.w);
        }
    }
    __syncthreads();

    // ---- Stage B: 128x64x64 GEMM, 8 edges x 8 dims per thread ----
    int te = tid & 15, td = tid >> 4;
    ull acc[4][8];
#pragma unroll
    for (int ep = 0; ep < 4; ep++)
#pragma unroll
        for (int dj = 0; dj < 8; dj++) acc[ep][dj] = 0ull;
    {
        const ulonglong2* hb = (const ulonglong2*)h1s2;
        const ulonglong2* wb = (const ulonglong2*)w2s;
#pragma unroll 8
        for (int k = 0; k < 64; k++) {
            ulonglong2 h01 = hb[k * 32 + 2 * te];
            ulonglong2 h23 = hb[k * 32 + 2 * te + 1];
            ulonglong2 w01 = wb[k * 32 + 4 * td];
            ulonglong2 w23 = wb[k * 32 + 4 * td + 1];
            ulonglong2 w45 = wb[k * 32 + 4 * td + 2];
            ulonglong2 w67 = wb[k * 32 + 4 * td + 3];
            ull hh0 = h01.x, hh1 = h01.y, hh2 = h23.x, hh3 = h23.y;
            ffma2(acc[0][0], w01.x, hh0); ffma2(acc[1][0], w01.x, hh1);
            ffma2(acc[2][0], w01.x, hh2); ffma2(acc[3][0], w01.x, hh3);
            ffma2(acc[0][1], w01.y, hh0); ffma2(acc[1][1], w01.y, hh1);
            ffma2(acc[2][1], w01.y, hh2); ffma2(acc[3][1], w01.y, hh3);
            ffma2(acc[0][2], w23.x, hh0); ffma2(acc[1][2], w23.x, hh1);
            ffma2(acc[2][2], w23.x, hh2); ffma2(acc[3][2], w23.x, hh3);
            ffma2(acc[0][3], w23.y, hh0); ffma2(acc[1][3], w23.y, hh1);
            ffma2(acc[2][3], w23.y, hh2); ffma2(acc[3][3], w23.y, hh3);
            ffma2(acc[0][4], w45.x, hh0); ffma2(acc[1][4], w45.x, hh1);
            ffma2(acc[2][4], w45.x, hh2); ffma2(acc[3][4], w45.x, hh3);
            ffma2(acc[0][5], w45.y, hh0); ffma2(acc[1][5], w45.y, hh1);
            ffma2(acc[2][5], w45.y, hh2); ffma2(acc[3][5], w45.y, hh3);
            ffma2(acc[0][6], w67.x, hh0); ffma2(acc[1][6], w67.x, hh1);
            ffma2(acc[2][6], w67.x, hh2); ffma2(acc[3][6], w67.x, hh3);
            ffma2(acc[0][7], w67.y, hh0); ffma2(acc[1][7], w67.y, hh1);
            ffma2(acc[2][7], w67.y, hh2); ffma2(acc[3][7], w67.y, hh3);
        }
    }

    // ---- Stage C: bias + relu, LN2 stats via partials, apply + scatter ----
    float b2r[8], gr[8], br[8];
    {
        float4 ba4 = ((const float4*)b2v)[2 * td];
        float4 bb4 = ((const float4*)b2v)[2 * td + 1];
        b2r[0] = ba4.x; b2r[1] = ba4.y; b2r[2] = ba4.z; b2r[3] = ba4.w;
        b2r[4] = bb4.x; b2r[5] = bb4.y; b2r[6] = bb4.z; b2r[7] = bb4.w;
        float4 ga4 = ((const float4*)gs)[2 * td];
        float4 gb4 = ((const float4*)gs)[2 * td + 1];
        gr[0] = ga4.x; gr[1] = ga4.y; gr[2] = ga4.z; gr[3] = ga4.w;
        gr[4] = gb4.x; gr[5] = gb4.y; gr[6] = gb4.z; gr[7] = gb4.w;
        float4 la4 = ((const float4*)bs)[2 * td];
        float4 lb4 = ((const float4*)bs)[2 * td + 1];
        br[0] = la4.x; br[1] = la4.y; br[2] = la4.z; br[3] = la4.w;
        br[4] = lb4.x; br[5] = lb4.y; br[6] = lb4.z; br[7] = lb4.w;
    }
    int dsts[8];
#pragma unroll
    for (int je = 0; je < 8; je++) dsts[je] = sdst[8 * te + je];
    __syncthreads();   // h1s2/sdst done; safe to overlay ps/pq/st2

    float vv[8][8];
#pragma unroll
    for (int ep = 0; ep < 4; ep++) {
#pragma unroll
        for (int dj = 0; dj < 8; dj++) {
            float lo, hi;
            unpack2(acc[ep][dj], lo, hi);
            vv[2 * ep][dj] = fmaxf(lo + b2r[dj], 0.f);
            vv[2 * ep + 1][dj] = fmaxf(hi + b2r[dj], 0.f);
        }
    }
#pragma unroll
    for (int je = 0; je < 8; je++) {
        float s = 0.f, q = 0.f;
#pragma unroll
        for (int dj = 0; dj < 8; dj++) {
            float x = vv[je][dj];
            s += x;
            q = fmaf(x, x, q);
        }
        ps[td * 128 + 8 * te + je] = s;
        pq[td * 128 + 8 * te + je] = q;
    }
    __syncthreads();
    {
        float s = 0.f, q = 0.f;
#pragma unroll
        for (int t = 0; t < 8; t++) {
            s += ps[t * 128 + tid];
            q += pq[t * 128 + tid];
        }
        float mean = s * (1.f / 64.f);
        float var = fmaf(-mean, mean, q * (1.f / 64.f));
        float r = rsqrtf(var + 1e-5f);
        st2[2 * tid] = r;
        st2[2 * tid + 1] = -mean * r;
    }
    __syncthreads();
#pragma unroll
    for (int je = 0; je < 8; je++) {
        int eb = 8 * te + je;
        float r2 = st2[2 * eb];
        float mr2 = st2[2 * eb + 1];
        int dn = dsts[je];
        float o[8];
#pragma unroll
        for (int dj = 0; dj < 8; dj++)
            o[dj] = fmaf(fmaf(vv[je][dj], r2, mr2), gr[dj], br[dj]);
        if (dn >= 0) {
            float* p = g_agg + (long)dn * 64 + 8 * td;
            asm volatile("red.global.add.v4.f32 [%0], {%1,%2,%3,%4};"
                         :: "l"(p), "f"(o[0]), "f"(o[1]), "f"(o[2]), "f"(o[3])
                         : "memory");
            asm volatile("red.global.add.v4.f32 [%0], {%1,%2,%3,%4};"
                         :: "l"(p + 4), "f"(o[4]), "f"(o[5]), "f"(o[6]), "f"(o[7])
                         : "memory");
        }
    }
}

// ---------------- qkv = h @ in_proj_w.T + b -------------------------------
__global__ void __launch_bounds__(192) qkv_kernel(const float* __restrict__ w,
                                                  const float* __restrict__ b, int N) {
    __shared__ __align__(16) float hs[16 * 64];
    int tid = threadIdx.x;
    int n0 = blockIdx.x * 16;
    for (int i = tid; i < 16 * 64; i += 192) hs[i] = g_agg[n0 * 64 + i];
    float wr[64];
    {
        const float4* p4 = (const float4*)(w + tid * 64);
#pragma unroll
        for (int k = 0; k < 16; k++) {
            float4 f = p4[k];
            wr[4 * k] = f.x; wr[4 * k + 1] = f.y; wr[4 * k + 2] = f.z; wr[4 * k + 3] = f.w;
        }
    }
    float br = b[tid];
    __syncthreads();
    int sec = tid / 64, wi = tid % 64, hh = wi / 16, dd = wi % 16;
    float* dst = sec == 0 ? g_q : (sec == 1 ? g_k : g_v);
#pragma unroll 4
    for (int nn = 0; nn < 16; nn++) {
        float acc = br;
#pragma unroll
        for (int k = 0; k < 16; k++) {
            float4 h = *(const float4*)&hs[nn * 64 + 4 * k];
            acc = fmaf(wr[4 * k], h.x, acc);
            acc = fmaf(wr[4 * k + 1], h.y, acc);
            acc = fmaf(wr[4 * k + 2], h.z, acc);
            acc = fmaf(wr[4 * k + 3], h.w, acc);
        }
        dst[hh * N * 16 + (n0 + nn) * 16 + dd] = acc;
    }
}

// ---------------- flash attention, f32x2, 4-way K-split ---------------------
__global__ void __launch_bounds__(128) attn_kernel(int N) {
    int hh = blockIdx.y;
    int part = threadIdx.x >> 5;
    int lane = threadIdx.x & 31;
    int qi = blockIdx.x * 32 + lane;
    const float* Q = g_q + hh * N * 16;
    const float* K = g_k + hh * N * 16;
    const float* V = g_v + hh * N * 16;

    __shared__ __align__(16) float Ks[4][64 * 16];
    __shared__ __align__(16) float Vs[4][64 * 16];
    __shared__ float mrg[3][32][18];

    ull q2[8];
    {
        const float4* qp = (const float4*)(Q + qi * 16);
#pragma unroll
        for (int u = 0; u < 4; u++) {
            float4 f = qp[u];
            q2[2 * u] = pack2(f.x * 0.25f, f.y * 0.25f);
            q2[2 * u + 1] = pack2(f.z * 0.25f, f.w * 0.25f);
        }
    }
    ull o2[8];
#pragma unroll
    for (int u = 0; u < 8; u++) o2[u] = 0ull;
    float m = -1e30f, l = 0.f;

    int j0 = part * (N >> 2);
    for (int kt = 0; kt < (N >> 2); kt += 64) {
        {
            const float4* ksrc = (const float4*)(K + (j0 + kt) * 16);
            const float4* vsrc = (const float4*)(V + (j0 + kt) * 16);
            float4* kdst = (float4*)Ks[part];
            float4* vdst = (float4*)Vs[part];
#pragma unroll
            for (int u = 0; u < 8; u++) {
                kdst[u * 32 + lane] = ksrc[u * 32 + lane];
                vdst[u * 32 + lane] = vsrc[u * 32 + lane];
            }
        }
        __syncwarp();
#pragma unroll 2
        for (int j = 0; j < 64; j++) {
            const ulonglong2* kr = (const ulonglong2*)&Ks[part][j * 16];
            ulonglong2 ka = kr[0], kb = kr[1], kc = kr[2], kd = kr[3];
            ull s2 = mul2(q2[0], ka.x);
            ffma2(s2, q2[1], ka.y);
            ffma2(s2, q2[2], kb.x);
            ffma2(s2, q2[3], kb.y);
            ffma2(s2, q2[4], kc.x);
            ffma2(s2, q2[5], kc.y);
            ffma2(s2, q2[6], kd.x);
            ffma2(s2, q2[7], kd.y);
            float slo, shi;
            unpack2(s2, slo, shi);
            float s = slo + shi;
            float nm = fmaxf(m, s);
            float p = __expf(s - nm);
            if (nm > m) {
                float corr = __expf(m - nm);
                ull c2 = pack2(corr, corr);
                l *= corr;
#pragma unroll
                for (int u = 0; u < 8; u++) o2[u] = mul2(o2[u], c2);
                m = nm;
            }
            l += p;
            ull p2 = pack2(p, p);
            const ulonglong2* vr = (const ulonglong2*)&Vs[part][j * 16];
            ulonglong2 va = vr[0], vb = vr[1], vc = vr[2], vd = vr[3];
            ffma2(o2[0], p2, va.x);
            ffma2(o2[1], p2, va.y);
            ffma2(o2[2], p2, vb.x);
            ffma2(o2[3], p2, vb.y);
            ffma2(o2[4], p2, vc.x);
            ffma2(o2[5], p2, vc.y);
            ffma2(o2[6], p2, vd.x);
            ffma2(o2[7], p2, vd.y);
        }
        __syncwarp();
    }

    if (part != 0) {
        float* d = &mrg[part - 1][lane][0];
        d[0] = m;
        d[1] = l;
#pragma unroll
        for (int u = 0; u < 8; u++) {
            float lo, hi;
            unpack2(o2[u], lo, hi);
            d[2 + 2 * u] = lo;
            d[3 + 2 * u] = hi;
        }
    }
    __syncthreads();
    if (part == 0) {
        float M = m;
#pragma unroll
        for (int p2i = 0; p2i < 3; p2i++) M = fmaxf(M, mrg[p2i][lane][0]);
        float c0 = __expf(m - M);
        float L = l * c0;
        float o[16];
#pragma unroll
        for (int u = 0; u < 8; u++) {
            float lo, hi;
            unpack2(o2[u], lo, hi);
            o[2 * u] = lo * c0;
            o[2 * u + 1] = hi * c0;
        }
#pragma unroll
        for (int p2i = 0; p2i < 3; p2i++) {
            const float* sp = &mrg[p2i][lane][0];
            float cp = __expf(sp[0] - M);
            L = fmaf(sp[1], cp, L);
#pragma unroll
            for (int c = 0; c < 16; c++) o[c] = fmaf(sp[2 + c], cp, o[c]);
        }
        float inv = 1.f / L;
#pragma unroll
        for (int c = 0; c < 16; c++) g_obuf[qi * 64 + hh * 16 + c] = o[c] * inv;
    }
}

// ---------------- out_proj + residual + LN + final linear --------------------
__global__ void __launch_bounds__(64) epi_kernel(
    const float* __restrict__ opw, const float* __restrict__ opb,
    const float* __restrict__ ang, const float* __restrict__ anb,
    const float* __restrict__ ow, const float* __restrict__ ob,
    float* __restrict__ out) {
    int d = threadIdx.x;
    int n0 = blockIdx.x * 8;
    __shared__ __align__(16) float os[8 * 64];
    __shared__ __align__(16) float ts[8 * 64];
    __shared__ float ps[8][8], pq[8][8];
    __shared__ float mv[8][2];

    for (int i = d; i < 8 * 64; i += 64) os[i] = g_obuf[n0 * 64 + i];
    float wr[64];
    {
        const float4* p4 = (const float4*)(opw + d * 64);
#pragma unroll
        for (int k = 0; k < 16; k++) {
            float4 f = p4[k];
            wr[4 * k] = f.x; wr[4 * k + 1] = f.y; wr[4 * k + 2] = f.z; wr[4 * k + 3] = f.w;
        }
    }
    float bb = opb[d];
    __syncthreads();
#pragma unroll
    for (int nn = 0; nn < 8; nn++) {
        float acc = bb;
#pragma unroll
        for (int k = 0; k < 16; k++) {
            float4 h = *(const float4*)&os[nn * 64 + 4 * k];
            acc = fmaf(wr[4 * k], h.x, acc);
            acc = fmaf(wr[4 * k + 1], h.y, acc);
            acc = fmaf(wr[4 * k + 2], h.z, acc);
            acc = fmaf(wr[4 * k + 3], h.w, acc);
        }
        ts[nn * 64 + d] = g_agg[(n0 + nn) * 64 + d] + acc;
    }
    __syncthreads();
    {
        int n = d >> 3, sg = d & 7;
        float s = 0.f, qq = 0.f;
#pragma unroll
        for (int t = 0; t < 8; t++) {
            float v2 = ts[n * 64 + sg * 8 + t];
            s += v2; qq += v2 * v2;
        }
        ps[n][sg] = s; pq[n][sg] = qq;
    }
    __syncthreads();
    if (d < 8) {
        float s = 0.f, qq = 0.f;
#pragma unroll
        for (int t = 0; t < 8; t++) { s += ps[d][t]; qq += pq[d][t]; }
        float mean = s * (1.f / 64.f);
        float var = qq * (1.f / 64.f) - mean * mean;
        mv[d][0] = mean;
        mv[d][1] = rsqrtf(var + 1e-5f);
    }
    __syncthreads();
    float gg = ang[d], gb = anb[d];
#pragma unroll
    for (int nn = 0; nn < 8; nn++)
        ts[nn * 64 + d] = (ts[nn * 64 + d] - mv[nn][0]) * mv[nn][1] * gg + gb;
    {
        const float4* p4 = (const float4*)(ow + d * 64);
#pragma unroll
        for (int k = 0; k < 16; k++) {
            float4 f = p4[k];
            wr[4 * k] = f.x; wr[4 * k + 1] = f.y; wr[4 * k + 2] = f.z; wr[4 * k + 3] = f.w;
        }
    }
    float bo = ob[d];
    __syncthreads();
#pragma unroll
    for (int nn = 0; nn < 8; nn++) {
        float acc = bo;
#pragma unroll
        for (int k = 0; k < 16; k++) {
            float4 h = *(const float4*)&ts[nn * 64 + 4 * k];
            acc = fmaf(wr[4 * k], h.x, acc);
            acc = fmaf(wr[4 * k + 1], h.y, acc);
            acc = fmaf(wr[4 * k + 2], h.z, acc);
            acc = fmaf(wr[4 * k + 3], h.w, acc);
        }
        out[(n0 + nn) * 64 + d] = acc;
    }
}

// ---------------- launch ----------------
extern "C" void kernel_launch(void* const* d_in, const int* in_sizes, int n_in,
                              void* d_out, int out_size) {
    const float* x        = (const float*)d_in[0];
    const float* eattr    = (const float*)d_in[1];
    const float* emb      = (const float*)d_in[2];
    const float* lin1_w   = (const float*)d_in[3];
    const float* lin1_b   = (const float*)d_in[4];
    const float* lay_w    = (const float*)d_in[5];
    const float* lay_b    = (const float*)d_in[6];
    const float* ln_g     = (const float*)d_in[7];
    const float* ln_b     = (const float*)d_in[8];
    const float* in_proj_w  = (const float*)d_in[9];
    const float* in_proj_b  = (const float*)d_in[10];
    const float* out_proj_w = (const float*)d_in[11];
    const float* out_proj_b = (const float*)d_in[12];
    const float* an_g     = (const float*)d_in[13];
    const float* an_b     = (const float*)d_in[14];
    const float* out_w    = (const float*)d_in[15];
    const float* out_b    = (const float*)d_in[16];
    const void*  ei       = d_in[17];
    const void*  ety      = d_in[18];

    int E = in_sizes[1];
    int N = in_sizes[0] / 6;

    cudaFuncSetAttribute(edge_kernel, cudaFuncAttributeMaxDynamicSharedMemorySize,
                         EDGE_SMEM);

    detect_kernel<<<1, 32>>>((const unsigned*)ei, (const unsigned*)ety);
    zero_kernel<<<(N * HID + 255) / 256, 256>>>(N * HID);
    packw_kernel<<<16, 256>>>(lay_w);
    prep_kernel<<<N, 64>>>(x, emb, lin1_w, lin1_b, ety);
    edge_kernel<<<(E + 127) / 128, 128, EDGE_SMEM>>>(ei, eattr, lin1_w, lay_b,
                                                     ln_g, ln_b, E);
    qkv_kernel<<<N / 16, 192>>>(in_proj_w, in_proj_b, N);
    attn_kernel<<<dim3(N / 32, 4), 128>>>(N);
    epi_kernel<<<N / 8, 64>>>(out_proj_w, out_proj_b, an_g, an_b, out_w, out_b,
                              (float*)d_out);
}